// round 4
// baseline (speedup 1.0000x reference)
#include <cuda_runtime.h>
#include <cstdint>
#include <cstddef>

// Problem constants
#define NB    2048
#define NE    512
#define NEMB  256
#define NAR   1024
#define NH256 256
#define NH32  32
#define NTYP  256

// Scratch (device globals — no allocation allowed)
__device__ float g_wc[NAR * NH32];     // W_fc1 @ W_fc2  (1024 x 32)
__device__ float g_bias2[NH32];        // b_fc1 @ W_fc2 + b_fc2
__device__ float g_v[(size_t)NB * NEMB]; // per-row key-projection vector
__device__ float g_c[NB];              // b_conv . query[b]

__device__ __forceinline__ float sigm(float x) { return 1.0f / (1.0f + expf(-x)); }

__device__ __forceinline__ uint32_t rotl32(uint32_t x, int r) {
    return (x << r) | (x >> (32 - r));
}

// Threefry-2x32, 20 rounds, key = (0, 42)  [jax.random.key(42)]
__device__ __forceinline__ void tf2x32_k42(uint32_t& x0, uint32_t& x1) {
    const uint32_t ks0 = 0u, ks1 = 42u, ks2 = 0x1BD11BF0u; // 0x1BD11BDA ^ 0 ^ 42
    x0 += ks0; x1 += ks1;
#define TF_R4(a,b,c,d) \
    x0 += x1; x1 = rotl32(x1,a); x1 ^= x0; \
    x0 += x1; x1 = rotl32(x1,b); x1 ^= x0; \
    x0 += x1; x1 = rotl32(x1,c); x1 ^= x0; \
    x0 += x1; x1 = rotl32(x1,d); x1 ^= x0;
    TF_R4(13,15,26,6)  x0 += ks1; x1 += ks2 + 1u;
    TF_R4(17,29,16,24) x0 += ks2; x1 += ks0 + 2u;
    TF_R4(13,15,26,6)  x0 += ks0; x1 += ks1 + 3u;
    TF_R4(17,29,16,24) x0 += ks1; x1 += ks2 + 4u;
    TF_R4(13,15,26,6)  x0 += ks2; x1 += ks0 + 5u;
#undef TF_R4
}

// JAX partitionable threefry random bits (default since jax 0.4.30):
// counter = 64-bit flat index; (hi, lo) -> threefry2x32 -> o0 ^ o1 for 32-bit.
__device__ __forceinline__ uint32_t jax_random_bits32(uint32_t idx) {
    uint32_t x0 = 0u;      // idx >> 32 == 0 (idx < 2^20)
    uint32_t x1 = idx;     // low word
    tf2x32_k42(x0, x1);
    return x0 ^ x1;
}

// ---------------------------------------------------------------------------
// Kernel P: g_wc = W_fc1 @ W_fc2 (1024x32), g_bias2 = b_fc1@W_fc2 + b_fc2
// ---------------------------------------------------------------------------
__global__ void __launch_bounds__(256) kP(
    const float* __restrict__ W_fc1, const float* __restrict__ b_fc1,
    const float* __restrict__ W_fc2, const float* __restrict__ b_fc2)
{
    int tid = threadIdx.x;
    int j = tid & 31;
    int a = blockIdx.x * 8 + (tid >> 5);
    const float4* w1 = (const float4*)(W_fc1 + (size_t)a * NH256);
    float acc = 0.0f;
#pragma unroll 4
    for (int kk = 0; kk < 64; kk++) {
        float4 wv = w1[kk];
        int base = kk * 128 + j;       // (4*kk)*32 + j
        acc = fmaf(wv.x, W_fc2[base],      acc);
        acc = fmaf(wv.y, W_fc2[base + 32], acc);
        acc = fmaf(wv.z, W_fc2[base + 64], acc);
        acc = fmaf(wv.w, W_fc2[base + 96], acc);
    }
    g_wc[a * NH32 + j] = acc;

    if (blockIdx.x == 0 && tid < 32) {
        float b2 = b_fc2[tid];
        for (int k = 0; k < NH256; k++)
            b2 = fmaf(b_fc1[k], W_fc2[k * NH32 + tid], b2);
        g_bias2[tid] = b2;
    }
}

// ---------------------------------------------------------------------------
// Kernel A: per batch row -> v[b] (256 floats) and c[b].
// BT=8 rows per block, grid 256 x 256 threads.
// ---------------------------------------------------------------------------
#define BT 8
__global__ void __launch_bounds__(256) kA(
    const float* __restrict__ ar,      const int* __restrict__ utm,
    const float* __restrict__ W_func,  const float* __restrict__ b_func,
    const float* __restrict__ W_conv,  const float* __restrict__ b_conv,
    const float* __restrict__ W_fc2,
    const float* __restrict__ lstm_k,  const float* __restrict__ lstm_b)
{
    __shared__ float    s_wc[8192];   // 32KB weight tile (W_fc2, then g_wc tiles)
    __shared__ float    s_t[BT * 256];// relu(mask@W_func + b_func)
    __shared__ uint32_t s_mb[256];    // bitmask of unit_types_mask per n
    __shared__ float    s_z[BT * 128];// lstm pre-activation
    __shared__ float    s_z2[BT * 32];
    __shared__ float    s_q[BT * 32];

    int tid = threadIdx.x;
    int b0 = blockIdx.x * BT;

    // pack masks: bit bb of s_mb[n] = unit_types_mask[b0+bb, n]
    {
        uint32_t bits = 0;
#pragma unroll
        for (int bb = 0; bb < BT; bb++)
            bits |= (utm[(size_t)(b0 + bb) * NTYP + tid] != 0 ? 1u : 0u) << bb;
        s_mb[tid] = bits;
    }
    __syncthreads();

    // func embed: t[bb] = relu(sum_{n:mask} W_func[n, k] + b_func[k]), k = tid
    {
        float bf = b_func[tid];
        float t[BT];
#pragma unroll
        for (int bb = 0; bb < BT; bb++) t[bb] = bf;
#pragma unroll 4
        for (int n = 0; n < NTYP; n++) {
            float w = W_func[(size_t)n * NH256 + tid];
            uint32_t bits = s_mb[n];
#pragma unroll
            for (int bb = 0; bb < BT; bb++)
                if ((bits >> bb) & 1u) t[bb] += w;
        }
#pragma unroll
        for (int bb = 0; bb < BT; bb++)
            s_t[bb * 256 + tid] = fmaxf(t[bb], 0.0f);
    }

    // stage W_fc2 (256x32) into s_wc
    for (int i = tid; i < 2048; i += 256)
        ((float4*)s_wc)[i] = ((const float4*)W_fc2)[i];
    __syncthreads();

    int bb = tid >> 5, j = tid & 31;
    float acc = g_bias2[j];

    // z2 contribution from func-embed @ W_fc2
    {
        const float4* tp = (const float4*)&s_t[bb * 256];
#pragma unroll 4
        for (int kk = 0; kk < 64; kk++) {
            float4 tv = tp[kk];
            int base = kk * 128 + j;
            acc = fmaf(tv.x, s_wc[base],      acc);
            acc = fmaf(tv.y, s_wc[base + 32], acc);
            acc = fmaf(tv.z, s_wc[base + 64], acc);
            acc = fmaf(tv.w, s_wc[base + 96], acc);
        }
    }

    // z2 contribution from ar @ (W_fc1@W_fc2), tiled over g_wc (4 tiles of 256 rows)
    for (int tile = 0; tile < 4; tile++) {
        __syncthreads();
        for (int i = tid; i < 2048; i += 256)
            ((float4*)s_wc)[i] = ((const float4*)g_wc)[tile * 2048 + i];
        __syncthreads();
        const float4* arp = (const float4*)(ar + (size_t)(b0 + bb) * NAR + tile * 256);
#pragma unroll 4
        for (int aa = 0; aa < 64; aa++) {
            float4 av = arp[aa];
            int base = aa * 128 + j;
            acc = fmaf(av.x, s_wc[base],      acc);
            acc = fmaf(av.y, s_wc[base + 32], acc);
            acc = fmaf(av.z, s_wc[base + 64], acc);
            acc = fmaf(av.w, s_wc[base + 96], acc);
        }
    }
    s_z2[bb * 32 + j] = acc;
    __syncthreads();

    // LSTM pre-activation z = z2 @ lstm_kernel + lstm_bias  (h0 = c0 = 0)
    for (int i = tid; i < BT * 128; i += 256) {
        int b2 = i >> 7, m = i & 127;
        float z = lstm_b[m];
        const float* z2p = &s_z2[b2 * 32];
#pragma unroll 4
        for (int jj = 0; jj < 32; jj++)
            z = fmaf(z2p[jj], lstm_k[jj * 128 + m], z);
        s_z[i] = z;
    }
    __syncthreads();

    // gates: c = sig(i)*tanh(g); q = sig(o)*tanh(c)
    {
        int b2 = tid >> 5, h = tid & 31;
        float zi = s_z[b2 * 128 + h];
        float zg = s_z[b2 * 128 + 64 + h];
        float zo = s_z[b2 * 128 + 96 + h];
        float c = sigm(zi) * tanhf(zg);
        float q = sigm(zo) * tanhf(c);
        s_q[tid] = q;
    }
    __syncthreads();

    // v[b, k] = sum_h W_conv[k, h] * q[h];  c[b] = b_conv . q
    {
        int k = tid;
        float4 wr[8];
        const float4* wp = (const float4*)(W_conv + (size_t)k * NH32);
#pragma unroll
        for (int i = 0; i < 8; i++) wr[i] = wp[i];
#pragma unroll
        for (int b2 = 0; b2 < BT; b2++) {
            const float* qp = &s_q[b2 * 32];
            float v = 0.0f;
#pragma unroll
            for (int i = 0; i < 8; i++) {
                v = fmaf(wr[i].x, qp[i * 4 + 0], v);
                v = fmaf(wr[i].y, qp[i * 4 + 1], v);
                v = fmaf(wr[i].z, qp[i * 4 + 2], v);
                v = fmaf(wr[i].w, qp[i * 4 + 3], v);
            }
            g_v[(size_t)(b0 + b2) * NEMB + k] = v;
        }
        if (tid < BT) {
            float c2 = 0.0f;
            for (int h = 0; h < 32; h++)
                c2 = fmaf(b_conv[h], s_q[tid * 32 + h], c2);
            g_c[b0 + tid] = c2;
        }
    }
}

// ---------------------------------------------------------------------------
// Kernel B: stream entity (1.07 GB), y[b,e] = entity[b,e,:].v[b] + c[b],
// fused softmax + threefry-gumbel categorical + masked writes.
// grid 2048 x 512 threads (warp per e, 2 e's per iteration).
// ---------------------------------------------------------------------------
__global__ void __launch_bounds__(512) kB(
    const float* __restrict__ entity, const int* __restrict__ tum,
    float* __restrict__ out, int write_tgt)
{
    __shared__ float s_v[256];
    __shared__ float s_y[512];
    __shared__ float s_red[16];
    __shared__ float s_rv[16];
    __shared__ int   s_ri[16];

    int b = blockIdx.x;
    int tid = threadIdx.x, lane = tid & 31, warp = tid >> 5;

    if (tid < 256) s_v[tid] = g_v[(size_t)b * NEMB + tid];
    __syncthreads();

    float4 va = ((const float4*)s_v)[lane];       // k = lane*4 .. +3
    float4 vb = ((const float4*)s_v)[32 + lane];  // k = 128 + lane*4 .. +3
    float cb = g_c[b];

    const float4* ep = ((const float4*)entity) + (size_t)b * (NE * NEMB / 4);

    for (int e0 = warp; e0 < NE; e0 += 32) {
        const float4* r0 = ep + (size_t)e0 * 64;
        const float4* r1 = ep + (size_t)(e0 + 16) * 64;
        float4 a0 = r0[lane], c0 = r0[32 + lane];
        float4 a1 = r1[lane], c1 = r1[32 + lane];
        float x0 = a0.x*va.x + a0.y*va.y + a0.z*va.z + a0.w*va.w
                 + c0.x*vb.x + c0.y*vb.y + c0.z*vb.z + c0.w*vb.w;
        float x1 = a1.x*va.x + a1.y*va.y + a1.z*va.z + a1.w*va.w
                 + c1.x*vb.x + c1.y*vb.y + c1.z*vb.z + c1.w*vb.w;
#pragma unroll
        for (int o = 16; o; o >>= 1) {
            x0 += __shfl_xor_sync(0xffffffffu, x0, o);
            x1 += __shfl_xor_sync(0xffffffffu, x1, o);
        }
        if (lane == 0) {
            s_y[e0]      = x0 + cb;
            s_y[e0 + 16] = x1 + cb;
        }
    }
    __syncthreads();

    float y = s_y[tid];   // tid == e (512 threads == E)

    // block max
    float m = y;
#pragma unroll
    for (int o = 16; o; o >>= 1) m = fmaxf(m, __shfl_xor_sync(0xffffffffu, m, o));
    if (lane == 0) s_red[warp] = m;
    __syncthreads();
    m = s_red[0];
#pragma unroll
    for (int i = 1; i < 16; i++) m = fmaxf(m, s_red[i]);

    // softmax
    float p = expf(y - m);
    float s = p;
#pragma unroll
    for (int o = 16; o; o >>= 1) s += __shfl_xor_sync(0xffffffffu, s, o);
    __syncthreads();
    if (lane == 0) s_red[warp] = s;
    __syncthreads();
    s = 0.0f;
#pragma unroll
    for (int i = 0; i < 16; i++) s += s_red[i];
    float prob = p / s;

    // JAX gumbel via partitionable threefry: bits for flat idx = b*512 + e
    unsigned idx = ((unsigned)b << 9) | (unsigned)tid;
    unsigned bits = jax_random_bits32(idx);
    float f = __uint_as_float(0x3f800000u | (bits >> 9)) - 1.0f;
    float u = (f == 0.0f) ? 1.17549435e-38f : f;
    float g = -logf(-logf(u));
    float val = prob + g;

    // argmax with first-index tie-break (matches jnp.argmax)
    int bi = tid;
#pragma unroll
    for (int o = 16; o; o >>= 1) {
        float ov = __shfl_xor_sync(0xffffffffu, val, o);
        int   oi = __shfl_xor_sync(0xffffffffu, bi,  o);
        if (ov > val || (ov == val && oi < bi)) { val = ov; bi = oi; }
    }
    if (lane == 0) { s_rv[warp] = val; s_ri[warp] = bi; }
    __syncthreads();

    int mask = tum[b];
    float mf = (float)mask;
    out[(size_t)b * NE + tid] = y * mf;   // TEMPERATURE = 1

    if (tid == 0 && write_tgt) {
        float bv = s_rv[0]; int bidx = s_ri[0];
#pragma unroll
        for (int i = 1; i < 16; i++) {
            if (s_rv[i] > bv || (s_rv[i] == bv && s_ri[i] < bidx)) {
                bv = s_rv[i]; bidx = s_ri[i];
            }
        }
        out[(size_t)NB * NE + b] = (float)(mask ? bidx : 0);
    }
}

// ---------------------------------------------------------------------------
extern "C" void kernel_launch(void* const* d_in, const int* in_sizes, int n_in,
                              void* d_out, int out_size)
{
    const float* ar      = (const float*)d_in[0];   // (2048, 1024) f32
    const int*   utm     = (const int*)  d_in[1];   // (2048, 256) i32
    const int*   tum     = (const int*)  d_in[2];   // (2048, 1) i32
    const float* entity  = (const float*)d_in[3];   // (2048, 512, 256) f32
    const float* W_func  = (const float*)d_in[4];   // (256, 256)
    const float* b_func  = (const float*)d_in[5];   // (256,)
    const float* W_conv  = (const float*)d_in[6];   // (256, 32)
    const float* b_conv  = (const float*)d_in[7];   // (32,)
    const float* W_fc1   = (const float*)d_in[8];   // (1024, 256)
    const float* b_fc1   = (const float*)d_in[9];   // (256,)
    const float* W_fc2   = (const float*)d_in[10];  // (256, 32)
    const float* b_fc2   = (const float*)d_in[11];  // (32,)
    const float* lstm_k  = (const float*)d_in[12];  // (32, 128)
    // d_in[13] = lstm_recurrent: unused (h0 = 0)
    const float* lstm_b  = (const float*)d_in[14];  // (128,)

    float* out = (float*)d_out;
    int write_tgt = (out_size >= NB * NE + NB) ? 1 : 0;

    kP<<<128, 256>>>(W_fc1, b_fc1, W_fc2, b_fc2);
    kA<<<256, 256>>>(ar, utm, W_func, b_func, W_conv, b_conv, W_fc2, lstm_k, lstm_b);
    kB<<<NB, 512>>>(entity, tum, out, write_tgt);
}

// round 6
// speedup vs baseline: 1.1280x; 1.1280x over previous
#include <cuda_runtime.h>
#include <cstdint>
#include <cstddef>

// Problem constants
#define NB    2048
#define NE    512
#define NEMB  256
#define NAR   1024
#define NH256 256
#define NH32  32
#define NTYP  256

// Scratch (device globals — no allocation allowed)
__device__ float g_wc[NAR * NH32];       // W_fc1 @ W_fc2  (1024 x 32)
__device__ float g_bias2[NH32];          // b_fc1 @ W_fc2 + b_fc2
__device__ float g_v[(size_t)NB * NEMB]; // per-row key-projection vector
__device__ float g_c[NB];                // b_conv . query[b]

__device__ __forceinline__ float sigm(float x) { return 1.0f / (1.0f + expf(-x)); }

__device__ __forceinline__ uint32_t rotl32(uint32_t x, int r) {
    return (x << r) | (x >> (32 - r));
}

// Threefry-2x32, 20 rounds, key = (0, 42)  [jax.random.key(42)]
__device__ __forceinline__ void tf2x32_k42(uint32_t& x0, uint32_t& x1) {
    const uint32_t ks0 = 0u, ks1 = 42u, ks2 = 0x1BD11BF0u; // 0x1BD11BDA ^ 0 ^ 42
    x0 += ks0; x1 += ks1;
#define TF_R4(a,b,c,d) \
    x0 += x1; x1 = rotl32(x1,a); x1 ^= x0; \
    x0 += x1; x1 = rotl32(x1,b); x1 ^= x0; \
    x0 += x1; x1 = rotl32(x1,c); x1 ^= x0; \
    x0 += x1; x1 = rotl32(x1,d); x1 ^= x0;
    TF_R4(13,15,26,6)  x0 += ks1; x1 += ks2 + 1u;
    TF_R4(17,29,16,24) x0 += ks2; x1 += ks0 + 2u;
    TF_R4(13,15,26,6)  x0 += ks0; x1 += ks1 + 3u;
    TF_R4(17,29,16,24) x0 += ks1; x1 += ks2 + 4u;
    TF_R4(13,15,26,6)  x0 += ks2; x1 += ks0 + 5u;
#undef TF_R4
}

// JAX partitionable threefry random bits (default since jax 0.4.30):
// counter = 64-bit flat index; (hi, lo) -> threefry2x32 -> o0 ^ o1 for 32-bit.
__device__ __forceinline__ uint32_t jax_random_bits32(uint32_t idx) {
    uint32_t x0 = 0u;      // idx >> 32 == 0 (idx < 2^20)
    uint32_t x1 = idx;     // low word
    tf2x32_k42(x0, x1);
    return x0 ^ x1;
}

// ---------------------------------------------------------------------------
// Kernel P: g_wc = W_fc1 @ W_fc2 (1024x32), g_bias2 = b_fc1@W_fc2 + b_fc2
// W_fc2 staged in smem; 4 independent accumulators to cut the FMA chain.
// grid 128 x 256 threads; thread = (a = bid*8 + tid/32, j = tid%32)
// ---------------------------------------------------------------------------
__global__ void __launch_bounds__(256) kP(
    const float* __restrict__ W_fc1, const float* __restrict__ b_fc1,
    const float* __restrict__ W_fc2, const float* __restrict__ b_fc2)
{
    __shared__ float s_w2[NH256 * NH32];  // 32KB
    int tid = threadIdx.x;
    for (int i = tid; i < 2048; i += 256)
        ((float4*)s_w2)[i] = ((const float4*)W_fc2)[i];
    __syncthreads();

    int j = tid & 31;
    int a = blockIdx.x * 8 + (tid >> 5);
    const float4* w1 = (const float4*)(W_fc1 + (size_t)a * NH256);

    float acc0 = 0.f, acc1 = 0.f, acc2 = 0.f, acc3 = 0.f;
#pragma unroll 4
    for (int kk = 0; kk < 64; kk += 4) {
        float4 v0 = w1[kk], v1 = w1[kk+1], v2 = w1[kk+2], v3 = w1[kk+3];
        int b0 = kk * 128 + j;
        acc0 = fmaf(v0.x, s_w2[b0      ], acc0);
        acc0 = fmaf(v0.y, s_w2[b0 +  32], acc0);
        acc0 = fmaf(v0.z, s_w2[b0 +  64], acc0);
        acc0 = fmaf(v0.w, s_w2[b0 +  96], acc0);
        acc1 = fmaf(v1.x, s_w2[b0 + 128], acc1);
        acc1 = fmaf(v1.y, s_w2[b0 + 160], acc1);
        acc1 = fmaf(v1.z, s_w2[b0 + 192], acc1);
        acc1 = fmaf(v1.w, s_w2[b0 + 224], acc1);
        acc2 = fmaf(v2.x, s_w2[b0 + 256], acc2);
        acc2 = fmaf(v2.y, s_w2[b0 + 288], acc2);
        acc2 = fmaf(v2.z, s_w2[b0 + 320], acc2);
        acc2 = fmaf(v2.w, s_w2[b0 + 352], acc2);
        acc3 = fmaf(v3.x, s_w2[b0 + 384], acc3);
        acc3 = fmaf(v3.y, s_w2[b0 + 416], acc3);
        acc3 = fmaf(v3.z, s_w2[b0 + 448], acc3);
        acc3 = fmaf(v3.w, s_w2[b0 + 480], acc3);
    }
    g_wc[a * NH32 + j] = (acc0 + acc1) + (acc2 + acc3);

    if (blockIdx.x == 0 && tid < 32) {
        float b2 = b_fc2[tid];
        float e0 = 0.f, e1 = 0.f;
        for (int k = 0; k < NH256; k += 2) {
            e0 = fmaf(b_fc1[k],     s_w2[k * NH32 + tid],        e0);
            e1 = fmaf(b_fc1[k + 1], s_w2[(k + 1) * NH32 + tid],  e1);
        }
        g_bias2[tid] = b2 + e0 + e1;
    }
}

// ---------------------------------------------------------------------------
// Kernel A: per batch row -> v[b] (256 floats) and c[b].
// BT=8 rows per block, grid 256 x 256 threads.
// ---------------------------------------------------------------------------
#define BT 8
__global__ void __launch_bounds__(256) kA(
    const float* __restrict__ ar,      const int* __restrict__ utm,
    const float* __restrict__ W_func,  const float* __restrict__ b_func,
    const float* __restrict__ W_conv,  const float* __restrict__ b_conv,
    const float* __restrict__ W_fc2,
    const float* __restrict__ lstm_k,  const float* __restrict__ lstm_b)
{
    __shared__ float    s_wc[8192];   // 32KB weight tile (W_fc2, then g_wc tiles)
    __shared__ float    s_t[BT * 256];// relu(mask@W_func + b_func)
    __shared__ uint32_t s_mb[256];    // bitmask of unit_types_mask per n
    __shared__ float    s_z[BT * 128];// lstm pre-activation
    __shared__ float    s_z2[BT * 32];
    __shared__ float    s_q[BT * 32];

    int tid = threadIdx.x;
    int b0 = blockIdx.x * BT;

    // pack masks: bit bb of s_mb[n] = unit_types_mask[b0+bb, n]
    {
        uint32_t bits = 0;
#pragma unroll
        for (int bb = 0; bb < BT; bb++)
            bits |= (utm[(size_t)(b0 + bb) * NTYP + tid] != 0 ? 1u : 0u) << bb;
        s_mb[tid] = bits;
    }
    __syncthreads();

    // func embed: t[bb] = relu(sum_{n:mask} W_func[n, k] + b_func[k]), k = tid
    {
        float bf = b_func[tid];
        float t[BT];
#pragma unroll
        for (int bb = 0; bb < BT; bb++) t[bb] = bf;
#pragma unroll 4
        for (int n = 0; n < NTYP; n++) {
            float w = W_func[(size_t)n * NH256 + tid];
            uint32_t bits = s_mb[n];
#pragma unroll
            for (int bb = 0; bb < BT; bb++)
                if ((bits >> bb) & 1u) t[bb] += w;
        }
#pragma unroll
        for (int bb = 0; bb < BT; bb++)
            s_t[bb * 256 + tid] = fmaxf(t[bb], 0.0f);
    }

    // stage W_fc2 (256x32) into s_wc
    for (int i = tid; i < 2048; i += 256)
        ((float4*)s_wc)[i] = ((const float4*)W_fc2)[i];
    __syncthreads();

    int bb = tid >> 5, j = tid & 31;
    float acc = g_bias2[j];

    // z2 contribution from func-embed @ W_fc2
    {
        const float4* tp = (const float4*)&s_t[bb * 256];
#pragma unroll 4
        for (int kk = 0; kk < 64; kk++) {
            float4 tv = tp[kk];
            int base = kk * 128 + j;
            acc = fmaf(tv.x, s_wc[base],      acc);
            acc = fmaf(tv.y, s_wc[base + 32], acc);
            acc = fmaf(tv.z, s_wc[base + 64], acc);
            acc = fmaf(tv.w, s_wc[base + 96], acc);
        }
    }

    // z2 contribution from ar @ (W_fc1@W_fc2), tiled over g_wc (4 tiles of 256 rows)
    for (int tile = 0; tile < 4; tile++) {
        __syncthreads();
        for (int i = tid; i < 2048; i += 256)
            ((float4*)s_wc)[i] = ((const float4*)g_wc)[tile * 2048 + i];
        __syncthreads();
        const float4* arp = (const float4*)(ar + (size_t)(b0 + bb) * NAR + tile * 256);
#pragma unroll 4
        for (int aa = 0; aa < 64; aa++) {
            float4 av = arp[aa];
            int base = aa * 128 + j;
            acc = fmaf(av.x, s_wc[base],      acc);
            acc = fmaf(av.y, s_wc[base + 32], acc);
            acc = fmaf(av.z, s_wc[base + 64], acc);
            acc = fmaf(av.w, s_wc[base + 96], acc);
        }
    }
    s_z2[bb * 32 + j] = acc;
    __syncthreads();

    // LSTM pre-activation z = z2 @ lstm_kernel + lstm_bias  (h0 = c0 = 0)
    for (int i = tid; i < BT * 128; i += 256) {
        int b2 = i >> 7, m = i & 127;
        float z = lstm_b[m];
        const float* z2p = &s_z2[b2 * 32];
#pragma unroll 4
        for (int jj = 0; jj < 32; jj++)
            z = fmaf(z2p[jj], lstm_k[jj * 128 + m], z);
        s_z[i] = z;
    }
    __syncthreads();

    // gates: c = sig(i)*tanh(g); q = sig(o)*tanh(c)
    {
        int b2 = tid >> 5, h = tid & 31;
        float zi = s_z[b2 * 128 + h];
        float zg = s_z[b2 * 128 + 64 + h];
        float zo = s_z[b2 * 128 + 96 + h];
        float c = sigm(zi) * tanhf(zg);
        float q = sigm(zo) * tanhf(c);
        s_q[tid] = q;
    }
    __syncthreads();

    // v[b, k] = sum_h W_conv[k, h] * q[h];  c[b] = b_conv . q
    {
        int k = tid;
        float4 wr[8];
        const float4* wp = (const float4*)(W_conv + (size_t)k * NH32);
#pragma unroll
        for (int i = 0; i < 8; i++) wr[i] = wp[i];
#pragma unroll
        for (int b2 = 0; b2 < BT; b2++) {
            const float* qp = &s_q[b2 * 32];
            float v = 0.0f;
#pragma unroll
            for (int i = 0; i < 8; i++) {
                v = fmaf(wr[i].x, qp[i * 4 + 0], v);
                v = fmaf(wr[i].y, qp[i * 4 + 1], v);
                v = fmaf(wr[i].z, qp[i * 4 + 2], v);
                v = fmaf(wr[i].w, qp[i * 4 + 3], v);
            }
            g_v[(size_t)(b0 + b2) * NEMB + k] = v;
        }
        if (tid < BT) {
            float c2 = 0.0f;
            for (int h = 0; h < 32; h++)
                c2 = fmaf(b_conv[h], s_q[tid * 32 + h], c2);
            g_c[b0 + tid] = c2;
        }
    }
}

// ---------------------------------------------------------------------------
// Kernel B: stream entity (1.07 GB), y[b,e] = entity[b,e,:].v[b] + c[b],
// fused softmax + threefry-gumbel categorical + masked writes.
// grid 2048 x 512 threads = 16 warps; each iteration a warp handles 4 e-rows
// at stride 16 (8 front-batched LDG.128 -> 4 interleaved shfl chains).
// 8 iterations x 16 warps x 4 rows = 512 rows.
// ---------------------------------------------------------------------------
__global__ void __launch_bounds__(512) kB(
    const float* __restrict__ entity, const int* __restrict__ tum,
    float* __restrict__ out, int write_tgt)
{
    __shared__ float s_v[256];
    __shared__ float s_y[512];
    __shared__ float s_red[16];
    __shared__ float s_rv[16];
    __shared__ int   s_ri[16];

    int b = blockIdx.x;
    int tid = threadIdx.x, lane = tid & 31, warp = tid >> 5;

    int mask = tum[b];            // early, overlaps with stream
    if (tid < 256) s_v[tid] = g_v[(size_t)b * NEMB + tid];
    __syncthreads();

    float4 va = ((const float4*)s_v)[lane];       // k = lane*4 .. +3
    float4 vb = ((const float4*)s_v)[32 + lane];  // k = 128 + lane*4 .. +3
    float cb = g_c[b];

    const float4* ep = ((const float4*)entity) + (size_t)b * (NE * NEMB / 4);

#pragma unroll
    for (int it = 0; it < 8; it++) {
        int e = it * 64 + warp;   // rows e, e+16, e+32, e+48 (16 warps)
        const float4* r0 = ep + (size_t)(e      ) * 64;
        const float4* r1 = ep + (size_t)(e + 16 ) * 64;
        const float4* r2 = ep + (size_t)(e + 32 ) * 64;
        const float4* r3 = ep + (size_t)(e + 48 ) * 64;
        float4 a0 = __ldcs(&r0[lane]), b0 = __ldcs(&r0[32 + lane]);
        float4 a1 = __ldcs(&r1[lane]), b1 = __ldcs(&r1[32 + lane]);
        float4 a2 = __ldcs(&r2[lane]), b2 = __ldcs(&r2[32 + lane]);
        float4 a3 = __ldcs(&r3[lane]), b3 = __ldcs(&r3[32 + lane]);

        float x0 = a0.x*va.x + a0.y*va.y + a0.z*va.z + a0.w*va.w
                 + b0.x*vb.x + b0.y*vb.y + b0.z*vb.z + b0.w*vb.w;
        float x1 = a1.x*va.x + a1.y*va.y + a1.z*va.z + a1.w*va.w
                 + b1.x*vb.x + b1.y*vb.y + b1.z*vb.z + b1.w*vb.w;
        float x2 = a2.x*va.x + a2.y*va.y + a2.z*va.z + a2.w*va.w
                 + b2.x*vb.x + b2.y*vb.y + b2.z*vb.z + b2.w*vb.w;
        float x3 = a3.x*va.x + a3.y*va.y + a3.z*va.z + a3.w*va.w
                 + b3.x*vb.x + b3.y*vb.y + b3.z*vb.z + b3.w*vb.w;

#pragma unroll
        for (int o = 16; o; o >>= 1) {
            x0 += __shfl_xor_sync(0xffffffffu, x0, o);
            x1 += __shfl_xor_sync(0xffffffffu, x1, o);
            x2 += __shfl_xor_sync(0xffffffffu, x2, o);
            x3 += __shfl_xor_sync(0xffffffffu, x3, o);
        }
        if (lane == 0) {
            s_y[e]      = x0 + cb;
            s_y[e + 16] = x1 + cb;
            s_y[e + 32] = x2 + cb;
            s_y[e + 48] = x3 + cb;
        }
    }
    __syncthreads();

    float y = s_y[tid];   // tid == e (512 threads == E)

    // block max
    float m = y;
#pragma unroll
    for (int o = 16; o; o >>= 1) m = fmaxf(m, __shfl_xor_sync(0xffffffffu, m, o));
    if (lane == 0) s_red[warp] = m;
    __syncthreads();
    m = s_red[0];
#pragma unroll
    for (int i = 1; i < 16; i++) m = fmaxf(m, s_red[i]);

    // softmax
    float p = expf(y - m);
    float s = p;
#pragma unroll
    for (int o = 16; o; o >>= 1) s += __shfl_xor_sync(0xffffffffu, s, o);
    __syncthreads();
    if (lane == 0) s_red[warp] = s;
    __syncthreads();
    s = 0.0f;
#pragma unroll
    for (int i = 0; i < 16; i++) s += s_red[i];
    float prob = p / s;

    // JAX gumbel via partitionable threefry: bits for flat idx = b*512 + e
    unsigned idx = ((unsigned)b << 9) | (unsigned)tid;
    unsigned bits = jax_random_bits32(idx);
    float f = __uint_as_float(0x3f800000u | (bits >> 9)) - 1.0f;
    float u = (f == 0.0f) ? 1.17549435e-38f : f;
    float g = -logf(-logf(u));
    float val = prob + g;

    // argmax with first-index tie-break (matches jnp.argmax)
    int bi = tid;
#pragma unroll
    for (int o = 16; o; o >>= 1) {
        float ov = __shfl_xor_sync(0xffffffffu, val, o);
        int   oi = __shfl_xor_sync(0xffffffffu, bi,  o);
        if (ov > val || (ov == val && oi < bi)) { val = ov; bi = oi; }
    }
    if (lane == 0) { s_rv[warp] = val; s_ri[warp] = bi; }
    __syncthreads();

    float mf = (float)mask;
    out[(size_t)b * NE + tid] = y * mf;   // TEMPERATURE = 1

    if (tid == 0 && write_tgt) {
        float bv = s_rv[0]; int bidx = s_ri[0];
#pragma unroll
        for (int i = 1; i < 16; i++) {
            if (s_rv[i] > bv || (s_rv[i] == bv && s_ri[i] < bidx)) {
                bv = s_rv[i]; bidx = s_ri[i];
            }
        }
        out[(size_t)NB * NE + b] = (float)(mask ? bidx : 0);
    }
}

// ---------------------------------------------------------------------------
extern "C" void kernel_launch(void* const* d_in, const int* in_sizes, int n_in,
                              void* d_out, int out_size)
{
    const float* ar      = (const float*)d_in[0];   // (2048, 1024) f32
    const int*   utm     = (const int*)  d_in[1];   // (2048, 256) i32
    const int*   tum     = (const int*)  d_in[2];   // (2048, 1) i32
    const float* entity  = (const float*)d_in[3];   // (2048, 512, 256) f32
    const float* W_func  = (const float*)d_in[4];   // (256, 256)
    const float* b_func  = (const float*)d_in[5];   // (256,)
    const float* W_conv  = (const float*)d_in[6];   // (256, 32)
    const float* b_conv  = (const float*)d_in[7];   // (32,)
    const float* W_fc1   = (const float*)d_in[8];   // (1024, 256)
    const float* b_fc1   = (const float*)d_in[9];   // (256,)
    const float* W_fc2   = (const float*)d_in[10];  // (256, 32)
    const float* b_fc2   = (const float*)d_in[11];  // (32,)
    const float* lstm_k  = (const float*)d_in[12];  // (32, 128)
    // d_in[13] = lstm_recurrent: unused (h0 = 0)
    const float* lstm_b  = (const float*)d_in[14];  // (128,)

    float* out = (float*)d_out;
    int write_tgt = (out_size >= NB * NE + NB) ? 1 : 0;

    kP<<<128, 256>>>(W_fc1, b_fc1, W_fc2, b_fc2);
    kA<<<256, 256>>>(ar, utm, W_func, b_func, W_conv, b_conv, W_fc2, lstm_k, lstm_b);
    kB<<<NB, 512>>>(entity, tum, out, write_tgt);
}

// round 7
// speedup vs baseline: 1.1721x; 1.0390x over previous
#include <cuda_runtime.h>
#include <cstdint>
#include <cstddef>

// Problem constants
#define NB    2048
#define NE    512
#define NEMB  256
#define NAR   1024
#define NH256 256
#define NH32  32
#define NTYP  256

// Scratch (device globals — no allocation allowed)
__device__ float g_wc[NAR * NH32];       // W_fc1 @ W_fc2  (1024 x 32)
__device__ float g_bias2[NH32];          // b_fc1 @ W_fc2 + b_fc2
__device__ float g_v[(size_t)NB * NEMB]; // per-row key-projection vector
__device__ float g_c[NB];                // b_conv . query[b]

__device__ __forceinline__ float sigm(float x) { return 1.0f / (1.0f + expf(-x)); }

__device__ __forceinline__ uint32_t rotl32(uint32_t x, int r) {
    return (x << r) | (x >> (32 - r));
}

// Threefry-2x32, 20 rounds, key = (0, 42)  [jax.random.key(42)]
__device__ __forceinline__ void tf2x32_k42(uint32_t& x0, uint32_t& x1) {
    const uint32_t ks0 = 0u, ks1 = 42u, ks2 = 0x1BD11BF0u; // 0x1BD11BDA ^ 0 ^ 42
    x0 += ks0; x1 += ks1;
#define TF_R4(a,b,c,d) \
    x0 += x1; x1 = rotl32(x1,a); x1 ^= x0; \
    x0 += x1; x1 = rotl32(x1,b); x1 ^= x0; \
    x0 += x1; x1 = rotl32(x1,c); x1 ^= x0; \
    x0 += x1; x1 = rotl32(x1,d); x1 ^= x0;
    TF_R4(13,15,26,6)  x0 += ks1; x1 += ks2 + 1u;
    TF_R4(17,29,16,24) x0 += ks2; x1 += ks0 + 2u;
    TF_R4(13,15,26,6)  x0 += ks0; x1 += ks1 + 3u;
    TF_R4(17,29,16,24) x0 += ks1; x1 += ks2 + 4u;
    TF_R4(13,15,26,6)  x0 += ks2; x1 += ks0 + 5u;
#undef TF_R4
}

// JAX partitionable threefry random bits (default since jax 0.4.30):
// counter = 64-bit flat index; (hi, lo) -> threefry2x32 -> o0 ^ o1 for 32-bit.
__device__ __forceinline__ uint32_t jax_random_bits32(uint32_t idx) {
    uint32_t x0 = 0u;      // idx >> 32 == 0 (idx < 2^20)
    uint32_t x1 = idx;     // low word
    tf2x32_k42(x0, x1);
    return x0 ^ x1;
}

// ---------------------------------------------------------------------------
// Kernel P v2: g_wc = W_fc1 @ W_fc2 (1024x32), g_bias2 = b_fc1@W_fc2 + b_fc2
// BOTH operands staged in smem via one front-batched coalesced burst
// (10 float4 per thread in flight -> single DRAM latency epoch).
// grid 128 x 256 threads; thread = (a = bid*8 + tid/32, j = tid%32)
// ---------------------------------------------------------------------------
__global__ void __launch_bounds__(256) kP(
    const float* __restrict__ W_fc1, const float* __restrict__ b_fc1,
    const float* __restrict__ W_fc2, const float* __restrict__ b_fc2)
{
    __shared__ float s_w2[NH256 * NH32];  // 32KB
    __shared__ float s_w1[8 * NH256];     // 8KB (this block's 8 W_fc1 rows)
    __shared__ float s_p[256];            // g_bias2 partials

    int tid = threadIdx.x;
    int a0 = blockIdx.x * 8;

    // front-batched coalesced staging: all 10 LDG.128 issued before any STS
    float4 t2[8], t1[2];
#pragma unroll
    for (int i = 0; i < 8; i++) t2[i] = ((const float4*)W_fc2)[tid + 256 * i];
#pragma unroll
    for (int i = 0; i < 2; i++)
        t1[i] = ((const float4*)(W_fc1 + (size_t)a0 * NH256))[tid + 256 * i];
#pragma unroll
    for (int i = 0; i < 8; i++) ((float4*)s_w2)[tid + 256 * i] = t2[i];
#pragma unroll
    for (int i = 0; i < 2; i++) ((float4*)s_w1)[tid + 256 * i] = t1[i];
    __syncthreads();

    int j = tid & 31;
    int aw = tid >> 5;                      // local a-row (0..7)
    const float4* w1 = (const float4*)(s_w1 + aw * NH256);

    float acc0 = 0.f, acc1 = 0.f, acc2 = 0.f, acc3 = 0.f;
#pragma unroll 4
    for (int kk = 0; kk < 64; kk += 4) {
        float4 v0 = w1[kk], v1 = w1[kk+1], v2 = w1[kk+2], v3 = w1[kk+3];
        int b0 = kk * 128 + j;
        acc0 = fmaf(v0.x, s_w2[b0      ], acc0);
        acc0 = fmaf(v0.y, s_w2[b0 +  32], acc0);
        acc0 = fmaf(v0.z, s_w2[b0 +  64], acc0);
        acc0 = fmaf(v0.w, s_w2[b0 +  96], acc0);
        acc1 = fmaf(v1.x, s_w2[b0 + 128], acc1);
        acc1 = fmaf(v1.y, s_w2[b0 + 160], acc1);
        acc1 = fmaf(v1.z, s_w2[b0 + 192], acc1);
        acc1 = fmaf(v1.w, s_w2[b0 + 224], acc1);
        acc2 = fmaf(v2.x, s_w2[b0 + 256], acc2);
        acc2 = fmaf(v2.y, s_w2[b0 + 288], acc2);
        acc2 = fmaf(v2.z, s_w2[b0 + 320], acc2);
        acc2 = fmaf(v2.w, s_w2[b0 + 352], acc2);
        acc3 = fmaf(v3.x, s_w2[b0 + 384], acc3);
        acc3 = fmaf(v3.y, s_w2[b0 + 416], acc3);
        acc3 = fmaf(v3.z, s_w2[b0 + 448], acc3);
        acc3 = fmaf(v3.w, s_w2[b0 + 480], acc3);
    }
    g_wc[(a0 + aw) * NH32 + j] = (acc0 + acc1) + (acc2 + acc3);

    // g_bias2: parallel over 256 threads (8 K-slices x 32 j), smem reduce
    if (blockIdx.x == 0) {
        int ks = tid >> 5;                  // K-slice 0..7
        float e = 0.f;
#pragma unroll 8
        for (int k = ks * 32; k < ks * 32 + 32; k++)
            e = fmaf(b_fc1[k], s_w2[k * NH32 + j], e);
        s_p[tid] = e;
        __syncthreads();
        if (tid < 32) {
            float b2 = b_fc2[tid];
#pragma unroll
            for (int s = 0; s < 8; s++) b2 += s_p[s * 32 + tid];
            g_bias2[tid] = b2;
        }
    }
}

// ---------------------------------------------------------------------------
// Kernel A: per batch row -> v[b] (256 floats) and c[b].
// BT=8 rows per block, grid 256 x 256 threads.
// ---------------------------------------------------------------------------
#define BT 8
__global__ void __launch_bounds__(256) kA(
    const float* __restrict__ ar,      const int* __restrict__ utm,
    const float* __restrict__ W_func,  const float* __restrict__ b_func,
    const float* __restrict__ W_conv,  const float* __restrict__ b_conv,
    const float* __restrict__ W_fc2,
    const float* __restrict__ lstm_k,  const float* __restrict__ lstm_b)
{
    __shared__ float    s_wc[8192];   // 32KB weight tile (W_fc2, then g_wc tiles)
    __shared__ float    s_t[BT * 256];// relu(mask@W_func + b_func)
    __shared__ uint32_t s_mb[256];    // bitmask of unit_types_mask per n
    __shared__ float    s_z[BT * 128];// lstm pre-activation
    __shared__ float    s_z2[BT * 32];
    __shared__ float    s_q[BT * 32];

    int tid = threadIdx.x;
    int b0 = blockIdx.x * BT;

    // pack masks: bit bb of s_mb[n] = unit_types_mask[b0+bb, n]
    {
        uint32_t bits = 0;
#pragma unroll
        for (int bb = 0; bb < BT; bb++)
            bits |= (utm[(size_t)(b0 + bb) * NTYP + tid] != 0 ? 1u : 0u) << bb;
        s_mb[tid] = bits;
    }
    __syncthreads();

    // func embed: t[bb] = relu(sum_{n:mask} W_func[n, k] + b_func[k]), k = tid
    {
        float bf = b_func[tid];
        float t[BT];
#pragma unroll
        for (int bb = 0; bb < BT; bb++) t[bb] = bf;
#pragma unroll 8
        for (int n = 0; n < NTYP; n++) {
            float w = W_func[(size_t)n * NH256 + tid];
            uint32_t bits = s_mb[n];
#pragma unroll
            for (int bb = 0; bb < BT; bb++)
                if ((bits >> bb) & 1u) t[bb] += w;
        }
#pragma unroll
        for (int bb = 0; bb < BT; bb++)
            s_t[bb * 256 + tid] = fmaxf(t[bb], 0.0f);
    }

    // stage W_fc2 (256x32) into s_wc
    for (int i = tid; i < 2048; i += 256)
        ((float4*)s_wc)[i] = ((const float4*)W_fc2)[i];
    __syncthreads();

    int bb = tid >> 5, j = tid & 31;
    float acc = g_bias2[j];

    // z2 contribution from func-embed @ W_fc2
    {
        const float4* tp = (const float4*)&s_t[bb * 256];
#pragma unroll 4
        for (int kk = 0; kk < 64; kk++) {
            float4 tv = tp[kk];
            int base = kk * 128 + j;
            acc = fmaf(tv.x, s_wc[base],      acc);
            acc = fmaf(tv.y, s_wc[base + 32], acc);
            acc = fmaf(tv.z, s_wc[base + 64], acc);
            acc = fmaf(tv.w, s_wc[base + 96], acc);
        }
    }

    // z2 contribution from ar @ (W_fc1@W_fc2), tiled over g_wc (4 tiles of 256 rows)
    for (int tile = 0; tile < 4; tile++) {
        __syncthreads();
        for (int i = tid; i < 2048; i += 256)
            ((float4*)s_wc)[i] = ((const float4*)g_wc)[tile * 2048 + i];
        __syncthreads();
        const float4* arp = (const float4*)(ar + (size_t)(b0 + bb) * NAR + tile * 256);
#pragma unroll 4
        for (int aa = 0; aa < 64; aa++) {
            float4 av = arp[aa];
            int base = aa * 128 + j;
            acc = fmaf(av.x, s_wc[base],      acc);
            acc = fmaf(av.y, s_wc[base + 32], acc);
            acc = fmaf(av.z, s_wc[base + 64], acc);
            acc = fmaf(av.w, s_wc[base + 96], acc);
        }
    }
    s_z2[bb * 32 + j] = acc;
    __syncthreads();

    // LSTM pre-activation z = z2 @ lstm_kernel + lstm_bias  (h0 = c0 = 0)
    for (int i = tid; i < BT * 128; i += 256) {
        int b2 = i >> 7, m = i & 127;
        float z = lstm_b[m];
        const float* z2p = &s_z2[b2 * 32];
#pragma unroll 4
        for (int jj = 0; jj < 32; jj++)
            z = fmaf(z2p[jj], lstm_k[jj * 128 + m], z);
        s_z[i] = z;
    }
    __syncthreads();

    // gates: c = sig(i)*tanh(g); q = sig(o)*tanh(c)
    {
        int b2 = tid >> 5, h = tid & 31;
        float zi = s_z[b2 * 128 + h];
        float zg = s_z[b2 * 128 + 64 + h];
        float zo = s_z[b2 * 128 + 96 + h];
        float c = sigm(zi) * tanhf(zg);
        float q = sigm(zo) * tanhf(c);
        s_q[tid] = q;
    }
    __syncthreads();

    // v[b, k] = sum_h W_conv[k, h] * q[h];  c[b] = b_conv . q
    {
        int k = tid;
        float4 wr[8];
        const float4* wp = (const float4*)(W_conv + (size_t)k * NH32);
#pragma unroll
        for (int i = 0; i < 8; i++) wr[i] = wp[i];
#pragma unroll
        for (int b2 = 0; b2 < BT; b2++) {
            const float* qp = &s_q[b2 * 32];
            float v = 0.0f;
#pragma unroll
            for (int i = 0; i < 8; i++) {
                v = fmaf(wr[i].x, qp[i * 4 + 0], v);
                v = fmaf(wr[i].y, qp[i * 4 + 1], v);
                v = fmaf(wr[i].z, qp[i * 4 + 2], v);
                v = fmaf(wr[i].w, qp[i * 4 + 3], v);
            }
            g_v[(size_t)(b0 + b2) * NEMB + k] = v;
        }
        if (tid < BT) {
            float c2 = 0.0f;
            for (int h = 0; h < 32; h++)
                c2 = fmaf(b_conv[h], s_q[tid * 32 + h], c2);
            g_c[b0 + tid] = c2;
        }
    }
}

// ---------------------------------------------------------------------------
// Kernel B: stream entity (1.07 GB), y[b,e] = entity[b,e,:].v[b] + c[b],
// fused softmax + threefry-gumbel categorical + masked writes.
// grid 2048 x 512 threads = 16 warps; each iteration a warp handles 4 e-rows
// at stride 16 (8 front-batched LDG.128 -> 4 interleaved shfl chains).
// 8 iterations x 16 warps x 4 rows = 512 rows.
// ---------------------------------------------------------------------------
__global__ void __launch_bounds__(512) kB(
    const float* __restrict__ entity, const int* __restrict__ tum,
    float* __restrict__ out, int write_tgt)
{
    __shared__ float s_v[256];
    __shared__ float s_y[512];
    __shared__ float s_red[16];
    __shared__ float s_rv[16];
    __shared__ int   s_ri[16];

    int b = blockIdx.x;
    int tid = threadIdx.x, lane = tid & 31, warp = tid >> 5;

    int mask = tum[b];            // early, overlaps with stream
    if (tid < 256) s_v[tid] = g_v[(size_t)b * NEMB + tid];
    __syncthreads();

    float4 va = ((const float4*)s_v)[lane];       // k = lane*4 .. +3
    float4 vb = ((const float4*)s_v)[32 + lane];  // k = 128 + lane*4 .. +3
    float cb = g_c[b];

    const float4* ep = ((const float4*)entity) + (size_t)b * (NE * NEMB / 4);

#pragma unroll
    for (int it = 0; it < 8; it++) {
        int e = it * 64 + warp;   // rows e, e+16, e+32, e+48 (16 warps)
        const float4* r0 = ep + (size_t)(e      ) * 64;
        const float4* r1 = ep + (size_t)(e + 16 ) * 64;
        const float4* r2 = ep + (size_t)(e + 32 ) * 64;
        const float4* r3 = ep + (size_t)(e + 48 ) * 64;
        float4 a0 = __ldcs(&r0[lane]), b0 = __ldcs(&r0[32 + lane]);
        float4 a1 = __ldcs(&r1[lane]), b1 = __ldcs(&r1[32 + lane]);
        float4 a2 = __ldcs(&r2[lane]), b2 = __ldcs(&r2[32 + lane]);
        float4 a3 = __ldcs(&r3[lane]), b3 = __ldcs(&r3[32 + lane]);

        float x0 = a0.x*va.x + a0.y*va.y + a0.z*va.z + a0.w*va.w
                 + b0.x*vb.x + b0.y*vb.y + b0.z*vb.z + b0.w*vb.w;
        float x1 = a1.x*va.x + a1.y*va.y + a1.z*va.z + a1.w*va.w
                 + b1.x*vb.x + b1.y*vb.y + b1.z*vb.z + b1.w*vb.w;
        float x2 = a2.x*va.x + a2.y*va.y + a2.z*va.z + a2.w*va.w
                 + b2.x*vb.x + b2.y*vb.y + b2.z*vb.z + b2.w*vb.w;
        float x3 = a3.x*va.x + a3.y*va.y + a3.z*va.z + a3.w*va.w
                 + b3.x*vb.x + b3.y*vb.y + b3.z*vb.z + b3.w*vb.w;

#pragma unroll
        for (int o = 16; o; o >>= 1) {
            x0 += __shfl_xor_sync(0xffffffffu, x0, o);
            x1 += __shfl_xor_sync(0xffffffffu, x1, o);
            x2 += __shfl_xor_sync(0xffffffffu, x2, o);
            x3 += __shfl_xor_sync(0xffffffffu, x3, o);
        }
        if (lane == 0) {
            s_y[e]      = x0 + cb;
            s_y[e + 16] = x1 + cb;
            s_y[e + 32] = x2 + cb;
            s_y[e + 48] = x3 + cb;
        }
    }
    __syncthreads();

    float y = s_y[tid];   // tid == e (512 threads == E)

    // block max
    float m = y;
#pragma unroll
    for (int o = 16; o; o >>= 1) m = fmaxf(m, __shfl_xor_sync(0xffffffffu, m, o));
    if (lane == 0) s_red[warp] = m;
    __syncthreads();
    m = s_red[0];
#pragma unroll
    for (int i = 1; i < 16; i++) m = fmaxf(m, s_red[i]);

    // softmax
    float p = expf(y - m);
    float s = p;
#pragma unroll
    for (int o = 16; o; o >>= 1) s += __shfl_xor_sync(0xffffffffu, s, o);
    __syncthreads();
    if (lane == 0) s_red[warp] = s;
    __syncthreads();
    s = 0.0f;
#pragma unroll
    for (int i = 0; i < 16; i++) s += s_red[i];
    float prob = p / s;

    // JAX gumbel via partitionable threefry: bits for flat idx = b*512 + e
    unsigned idx = ((unsigned)b << 9) | (unsigned)tid;
    unsigned bits = jax_random_bits32(idx);
    float f = __uint_as_float(0x3f800000u | (bits >> 9)) - 1.0f;
    float u = (f == 0.0f) ? 1.17549435e-38f : f;
    float g = -logf(-logf(u));
    float val = prob + g;

    // argmax with first-index tie-break (matches jnp.argmax)
    int bi = tid;
#pragma unroll
    for (int o = 16; o; o >>= 1) {
        float ov = __shfl_xor_sync(0xffffffffu, val, o);
        int   oi = __shfl_xor_sync(0xffffffffu, bi,  o);
        if (ov > val || (ov == val && oi < bi)) { val = ov; bi = oi; }
    }
    if (lane == 0) { s_rv[warp] = val; s_ri[warp] = bi; }
    __syncthreads();

    float mf = (float)mask;
    out[(size_t)b * NE + tid] = y * mf;   // TEMPERATURE = 1

    if (tid == 0 && write_tgt) {
        float bv = s_rv[0]; int bidx = s_ri[0];
#pragma unroll
        for (int i = 1; i < 16; i++) {
            if (s_rv[i] > bv || (s_rv[i] == bv && s_ri[i] < bidx)) {
                bv = s_rv[i]; bidx = s_ri[i];
            }
        }
        out[(size_t)NB * NE + b] = (float)(mask ? bidx : 0);
    }
}

// ---------------------------------------------------------------------------
extern "C" void kernel_launch(void* const* d_in, const int* in_sizes, int n_in,
                              void* d_out, int out_size)
{
    const float* ar      = (const float*)d_in[0];   // (2048, 1024) f32
    const int*   utm     = (const int*)  d_in[1];   // (2048, 256) i32
    const int*   tum     = (const int*)  d_in[2];   // (2048, 1) i32
    const float* entity  = (const float*)d_in[3];   // (2048, 512, 256) f32
    const float* W_func  = (const float*)d_in[4];   // (256, 256)
    const float* b_func  = (const float*)d_in[5];   // (256,)
    const float* W_conv  = (const float*)d_in[6];   // (256, 32)
    const float* b_conv  = (const float*)d_in[7];   // (32,)
    const float* W_fc1   = (const float*)d_in[8];   // (1024, 256)
    const float* b_fc1   = (const float*)d_in[9];   // (256,)
    const float* W_fc2   = (const float*)d_in[10];  // (256, 32)
    const float* b_fc2   = (const float*)d_in[11];  // (32,)
    const float* lstm_k  = (const float*)d_in[12];  // (32, 128)
    // d_in[13] = lstm_recurrent: unused (h0 = 0)
    const float* lstm_b  = (const float*)d_in[14];  // (128,)

    float* out = (float*)d_out;
    int write_tgt = (out_size >= NB * NE + NB) ? 1 : 0;

    kP<<<128, 256>>>(W_fc1, b_fc1, W_fc2, b_fc2);
    kA<<<256, 256>>>(ar, utm, W_func, b_func, W_conv, b_conv, W_fc2, lstm_k, lstm_b);
    kB<<<NB, 512>>>(entity, tum, out, write_tgt);
}